// round 8
// baseline (speedup 1.0000x reference)
#include <cuda_runtime.h>
#include <cuda_bf16.h>
#include <cstdint>

// GaussianKernel: N=32, R=128, F=128
// Gram form: D[i,j] = ||u_i||^2 - 2 u_i.v_j + ||v_j||^2,  u = x1 - mean, v = x2
// out = softmax_j( exp( exp(-D/(2 sigma^2)) ) )
//
// 128 blocks (1/SM), 256 threads = 8 warps.
// Warp w: 8 i-rows (group w&3), 2 j-quarters (half h=w>>2, q in {2h,2h+1}).
// normu fused into x1 fill (register squares + shfl). normv folded into main loop.

#define N_B 32
#define R_DIM 128
#define F_DIM 128
#define TIB 32
#define SSTR 132        // padded row stride (floats): conflict-free 16B accesses

__device__ __forceinline__ unsigned long long f32x2_fma(unsigned long long a, unsigned long long b, unsigned long long c) {
    unsigned long long r;
    asm("fma.rn.f32x2 %0, %1, %2, %3;" : "=l"(r) : "l"(a), "l"(b), "l"(c));
    return r;
}
__device__ __forceinline__ void f32x2_unpack(unsigned long long u, float& lo, float& hi) {
    asm("mov.b64 {%0, %1}, %2;" : "=f"(lo), "=f"(hi) : "l"(u));
}

// exp(x) for x in [0,1]: Taylor degree 10 (Horner). |err| <= 2.8e-8 abs.
__device__ __forceinline__ float exp01(float x) {
    float r = fmaf(2.75573192e-7f, x, 2.75573192e-6f);
    r = fmaf(r, x, 2.48015873e-5f);
    r = fmaf(r, x, 1.98412698e-4f);
    r = fmaf(r, x, 1.38888889e-3f);
    r = fmaf(r, x, 8.33333333e-3f);
    r = fmaf(r, x, 4.16666667e-2f);
    r = fmaf(r, x, 1.66666667e-1f);
    r = fmaf(r, x, 0.5f);
    r = fmaf(r, x, 1.0f);
    r = fmaf(r, x, 1.0f);
    return r;
}

__global__ void __launch_bounds__(256)
gaussian_gram_v7(const float4* __restrict__ x1,
                 const float4* __restrict__ x2,
                 const float* __restrict__ sigma,
                 const float* __restrict__ mean,
                 float* __restrict__ out) {
    extern __shared__ float smem[];
    float* x2s   = smem;                          // [128][132]  v
    float* x1s   = x2s + R_DIM * SSTR;            // [32][132]   u = x1 - mean
    float* normu = x1s + TIB * SSTR;              // [32]
    float* pd    = normu + TIB;                   // [32][2] half-sums

    const int n    = blockIdx.y;
    const int i0   = blockIdx.x * TIB;
    const int t    = threadIdx.x;
    const int lane = t & 31;
    const int w    = t >> 5;                      // 0..7
    const int r0   = (w & 3) * 8;                 // row group base
    const int h    = w >> 2;                      // j-half (q = 2h, 2h+1)

    const float mn = mean[0];
    const float sg = sigma[0];
    const float inv2s2 = 1.0f / (2.0f * sg * sg);

    // ---- fill v = x2[n] into padded smem (coalesced float4) ----
    const float4* x2g = x2 + (size_t)n * (R_DIM * F_DIM / 4);
    #pragma unroll
    for (int it = 0; it < (R_DIM * F_DIM / 4) / 256; ++it) {
        int idx4 = t + 256 * it;                  // 0..4095
        int row  = idx4 >> 5;
        int c4   = idx4 & 31;
        *(float4*)&x2s[row * SSTR + c4 * 4] = x2g[idx4];
    }

    // ---- fill u = x1 - mean, fused normu ----
    // thread t: row r = t>>3, 16 consecutive floats (chunk c = t&7)
    {
        const int r = t >> 3, c = t & 7;
        const float4* src = x1 + ((size_t)(n * R_DIM + i0 + r) * F_DIM + c * 16) / 4;
        float sq = 0.0f;
        #pragma unroll
        for (int q = 0; q < 4; ++q) {
            float4 v = src[q];
            float4 u = make_float4(v.x - mn, v.y - mn, v.z - mn, v.w - mn);
            sq = fmaf(u.x, u.x, sq);
            sq = fmaf(u.y, u.y, sq);
            sq = fmaf(u.z, u.z, sq);
            sq = fmaf(u.w, u.w, sq);
            *(float4*)&x1s[r * SSTR + c * 16 + q * 4] = u;
        }
        sq += __shfl_xor_sync(0xffffffffu, sq, 1);
        sq += __shfl_xor_sync(0xffffffffu, sq, 2);
        sq += __shfl_xor_sync(0xffffffffu, sq, 4);
        if ((t & 7) == 0) normu[r] = sq;
    }
    __syncthreads();

    // ---- main loop: 8i x 2j register tile, fold ||v_j||^2 ----
    unsigned long long acc[8][2];
    #pragma unroll
    for (int r = 0; r < 8; ++r) { acc[r][0] = 0ull; acc[r][1] = 0ull; }
    unsigned long long accv0 = 0ull, accv1 = 0ull;

    const ulonglong2* brow = (const ulonglong2*)&x2s[lane * SSTR];
    const float* arow = &x1s[r0 * SSTR];
    const int bq = 32 * SSTR / 4;                 // ull2 units per 32 rows
    const int o0 = (2 * h) * bq, o1 = (2 * h + 1) * bq;

    #pragma unroll 2
    for (int f4 = 0; f4 < F_DIM / 4; ++f4) {
        ulonglong2 b0 = brow[o0 + f4];
        ulonglong2 b1 = brow[o1 + f4];
        accv0 = f32x2_fma(b0.x, b0.x, accv0);
        accv0 = f32x2_fma(b0.y, b0.y, accv0);
        accv1 = f32x2_fma(b1.x, b1.x, accv1);
        accv1 = f32x2_fma(b1.y, b1.y, accv1);
        #pragma unroll
        for (int r = 0; r < 8; ++r) {
            ulonglong2 a = *(const ulonglong2*)&arow[r * SSTR + f4 * 4];
            acc[r][0] = f32x2_fma(a.x, b0.x, acc[r][0]);
            acc[r][0] = f32x2_fma(a.y, b0.y, acc[r][0]);
            acc[r][1] = f32x2_fma(a.x, b1.x, acc[r][1]);
            acc[r][1] = f32x2_fma(a.y, b1.y, acc[r][1]);
        }
    }

    float lo, hi;
    f32x2_unpack(accv0, lo, hi);
    const float nv0 = lo + hi;
    f32x2_unpack(accv1, lo, hi);
    const float nv1 = lo + hi;

    // ---- epilogue: kernel value, poly outer exp, half-row sums ----
    float ex[8][2];
    #pragma unroll
    for (int r = 0; r < 8; ++r) {
        const float nu = normu[r0 + r];
        f32x2_unpack(acc[r][0], lo, hi);
        float D0 = nu + nv0 - 2.0f * (lo + hi);
        f32x2_unpack(acc[r][1], lo, hi);
        float D1 = nu + nv1 - 2.0f * (lo + hi);
        float k0 = __expf(-D0 * inv2s2);          // in (0,1]
        float k1 = __expf(-D1 * inv2s2);
        ex[r][0] = exp01(k0);
        ex[r][1] = exp01(k1);
        float s = ex[r][0] + ex[r][1];
        #pragma unroll
        for (int o = 16; o > 0; o >>= 1)
            s += __shfl_xor_sync(0xffffffffu, s, o);
        if (lane == 0) pd[(r0 + r) * 2 + h] = s;
    }
    __syncthreads();

    // ---- normalize and write ----
    float* outbase = out + ((size_t)n * R_DIM + i0 + r0) * R_DIM;
    #pragma unroll
    for (int r = 0; r < 8; ++r) {
        float tot = pd[(r0 + r) * 2] + pd[(r0 + r) * 2 + 1];
        float inv = __fdividef(1.0f, tot);
        outbase[r * R_DIM + lane + 32 * (2 * h)]     = ex[r][0] * inv;
        outbase[r * R_DIM + lane + 32 * (2 * h + 1)] = ex[r][1] * inv;
    }
}

extern "C" void kernel_launch(void* const* d_in, const int* in_sizes, int n_in,
                              void* d_out, int out_size) {
    const float4* x1    = (const float4*)d_in[0];
    const float4* x2    = (const float4*)d_in[1];
    const float*  sigma = (const float*)d_in[2];
    const float*  mean  = (const float*)d_in[3];
    float* out = (float*)d_out;

    const int smem_bytes = (R_DIM * SSTR + TIB * SSTR + TIB + TIB * 2) * (int)sizeof(float);
    cudaFuncSetAttribute(gaussian_gram_v7,
                         cudaFuncAttributeMaxDynamicSharedMemorySize, smem_bytes);

    dim3 grid(R_DIM / TIB, N_B);   // (4, 32) = 128 blocks -> 1 per SM
    dim3 block(256);
    gaussian_gram_v7<<<grid, block, smem_bytes>>>(x1, x2, sigma, mean, out);
}

// round 9
// speedup vs baseline: 1.5627x; 1.5627x over previous
#include <cuda_runtime.h>
#include <cuda_bf16.h>
#include <cstdint>

// GaussianKernel: N=32, R=128, F=128
// Gram form: D[i,j] = ||u_i||^2 - 2 u_i.v_j + ||v_j||^2,  u = x1 - mean, v = x2
// out = softmax_j( exp( exp(-D/(2 sigma^2)) ) )
//
// 128 blocks (1/SM), 256 threads = 8 warps. 4i x 4j register tile per thread.
// Software-pipelined inner loop (prefetch next b/a during fma block).
// Batched-MLP fill. Poly outer exp. Warp-local softmax.

#define N_B 32
#define R_DIM 128
#define F_DIM 128
#define TIB 32
#define X2_STRIDE 132   // padded row stride (floats): conflict-free LDS.128

__device__ __forceinline__ unsigned long long f32x2_fma(unsigned long long a, unsigned long long b, unsigned long long c) {
    unsigned long long r;
    asm("fma.rn.f32x2 %0, %1, %2, %3;" : "=l"(r) : "l"(a), "l"(b), "l"(c));
    return r;
}
__device__ __forceinline__ void f32x2_unpack(unsigned long long u, float& lo, float& hi) {
    asm("mov.b64 {%0, %1}, %2;" : "=f"(lo), "=f"(hi) : "l"(u));
}

// exp(x) for x in [0,1]: Taylor degree 10 (Horner). |err| <= 2.8e-8 abs.
__device__ __forceinline__ float exp01(float x) {
    float r = fmaf(2.75573192e-7f, x, 2.75573192e-6f);
    r = fmaf(r, x, 2.48015873e-5f);
    r = fmaf(r, x, 1.98412698e-4f);
    r = fmaf(r, x, 1.38888889e-3f);
    r = fmaf(r, x, 8.33333333e-3f);
    r = fmaf(r, x, 4.16666667e-2f);
    r = fmaf(r, x, 1.66666667e-1f);
    r = fmaf(r, x, 0.5f);
    r = fmaf(r, x, 1.0f);
    r = fmaf(r, x, 1.0f);
    return r;
}

__global__ void __launch_bounds__(256)
gaussian_gram_pipe(const float4* __restrict__ x1,
                   const float4* __restrict__ x2,
                   const float* __restrict__ sigma,
                   const float* __restrict__ mean,
                   float* __restrict__ out) {
    extern __shared__ float smem[];
    float* x2s   = smem;                         // [128][132]  v
    float* x1s   = x2s + R_DIM * X2_STRIDE;      // [32][128]   u = x1 - mean
    float* normu = x1s + TIB * F_DIM;            // [32]

    const int n    = blockIdx.y;
    const int i0   = blockIdx.x * TIB;
    const int t    = threadIdx.x;
    const int lane = t & 31;
    const int warp = t >> 5;                     // 0..7 -> i-rows 4w..4w+3

    const float mn = mean[0];
    const float sg = sigma[0];
    const float inv2s2 = 1.0f / (2.0f * sg * sg);

    // ---- batched fill: issue ALL LDGs first (MLP=18), then all STS ----
    {
        const float4* x2g = x2 + (size_t)n * (R_DIM * F_DIM / 4);
        const float4* x1g = x1 + ((size_t)n * R_DIM + i0) * (F_DIM / 4);
        float4 vb[16], ub[2];
        #pragma unroll
        for (int it = 0; it < 16; ++it) vb[it] = x2g[t + 256 * it];
        #pragma unroll
        for (int it = 0; it < 2; ++it)  ub[it] = x1g[t + 256 * it];

        #pragma unroll
        for (int it = 0; it < 16; ++it) {
            int idx4 = t + 256 * it;
            int row  = idx4 >> 5;
            int c4   = idx4 & 31;
            *(float4*)&x2s[row * X2_STRIDE + c4 * 4] = vb[it];
        }
        #pragma unroll
        for (int it = 0; it < 2; ++it) {
            int idx4 = t + 256 * it;
            float4 v = ub[it];
            *(float4*)&x1s[idx4 * 4] = make_float4(v.x - mn, v.y - mn, v.z - mn, v.w - mn);
        }
    }
    __syncthreads();

    // ---- normu: thread t -> row r = t>>3, 16-float chunk c = t&7 ----
    {
        int r = t >> 3, c = t & 7;
        const ulonglong2* up = (const ulonglong2*)&x1s[r * F_DIM + c * 16];
        unsigned long long accu = 0ull;
        #pragma unroll
        for (int q = 0; q < 4; ++q) {
            ulonglong2 a = up[q];
            accu = f32x2_fma(a.x, a.x, accu);
            accu = f32x2_fma(a.y, a.y, accu);
        }
        float lo, hi; f32x2_unpack(accu, lo, hi);
        float s = lo + hi;
        s += __shfl_xor_sync(0xffffffffu, s, 1);
        s += __shfl_xor_sync(0xffffffffu, s, 2);
        s += __shfl_xor_sync(0xffffffffu, s, 4);
        if ((t & 7) == 0) normu[r] = s;
    }
    __syncthreads();

    // ---- main loop: 4i x 4j tile, software-pipelined (prefetch dist 1) ----
    unsigned long long acc[4][4];
    #pragma unroll
    for (int r = 0; r < 4; ++r)
        #pragma unroll
        for (int q = 0; q < 4; ++q) acc[r][q] = 0ull;
    unsigned long long accv[4] = {0ull, 0ull, 0ull, 0ull};

    const ulonglong2* brow = (const ulonglong2*)&x2s[lane * X2_STRIDE];
    const float* arow = &x1s[warp * 4 * F_DIM];
    const int bq_stride = 32 * X2_STRIDE / 4;

    ulonglong2 bc[4], ac[4], bn[4], an[4];
    #pragma unroll
    for (int q = 0; q < 4; ++q) bc[q] = brow[q * bq_stride];
    #pragma unroll
    for (int r = 0; r < 4; ++r) ac[r] = *(const ulonglong2*)&arow[r * F_DIM];

    #pragma unroll 8
    for (int f4 = 0; f4 < F_DIM / 4; ++f4) {
        // prefetch next iteration's operands
        if (f4 + 1 < F_DIM / 4) {
            #pragma unroll
            for (int q = 0; q < 4; ++q) bn[q] = brow[q * bq_stride + f4 + 1];
            #pragma unroll
            for (int r = 0; r < 4; ++r) an[r] = *(const ulonglong2*)&arow[r * F_DIM + (f4 + 1) * 4];
        }
        // fma block on current
        #pragma unroll
        for (int q = 0; q < 4; ++q) {
            accv[q] = f32x2_fma(bc[q].x, bc[q].x, accv[q]);
            accv[q] = f32x2_fma(bc[q].y, bc[q].y, accv[q]);
        }
        #pragma unroll
        for (int r = 0; r < 4; ++r)
            #pragma unroll
            for (int q = 0; q < 4; ++q) {
                acc[r][q] = f32x2_fma(ac[r].x, bc[q].x, acc[r][q]);
                acc[r][q] = f32x2_fma(ac[r].y, bc[q].y, acc[r][q]);
            }
        #pragma unroll
        for (int q = 0; q < 4; ++q) bc[q] = bn[q];
        #pragma unroll
        for (int r = 0; r < 4; ++r) ac[r] = an[r];
    }

    // ---- epilogue ----
    float nv[4];
    #pragma unroll
    for (int q = 0; q < 4; ++q) {
        float lo, hi; f32x2_unpack(accv[q], lo, hi);
        nv[q] = lo + hi;
    }
    float nu[4];
    #pragma unroll
    for (int r = 0; r < 4; ++r) nu[r] = normu[warp * 4 + r];

    float* outbase = out + ((size_t)n * R_DIM + i0 + warp * 4) * R_DIM;

    #pragma unroll
    for (int r = 0; r < 4; ++r) {
        float ex[4];
        float s = 0.0f;
        #pragma unroll
        for (int q = 0; q < 4; ++q) {
            float lo, hi; f32x2_unpack(acc[r][q], lo, hi);
            float D = nu[r] + nv[q] - 2.0f * (lo + hi);
            float k = __expf(-D * inv2s2);       // in (0,1]
            ex[q] = exp01(k);                    // poly exp on FMA pipe
            s += ex[q];
        }
        #pragma unroll
        for (int o = 16; o > 0; o >>= 1)
            s += __shfl_xor_sync(0xffffffffu, s, o);
        const float inv = __fdividef(1.0f, s);
        #pragma unroll
        for (int q = 0; q < 4; ++q)
            outbase[r * R_DIM + lane + 32 * q] = ex[q] * inv;
    }
}

extern "C" void kernel_launch(void* const* d_in, const int* in_sizes, int n_in,
                              void* d_out, int out_size) {
    const float4* x1    = (const float4*)d_in[0];
    const float4* x2    = (const float4*)d_in[1];
    const float*  sigma = (const float*)d_in[2];
    const float*  mean  = (const float*)d_in[3];
    float* out = (float*)d_out;

    const int smem_bytes = (R_DIM * X2_STRIDE + TIB * F_DIM + TIB) * (int)sizeof(float);
    cudaFuncSetAttribute(gaussian_gram_pipe,
                         cudaFuncAttributeMaxDynamicSharedMemorySize, smem_bytes);

    dim3 grid(R_DIM / TIB, N_B);   // (4, 32) = 128 blocks -> 1 per SM
    dim3 block(256);
    gaussian_gram_pipe<<<grid, block, smem_bytes>>>(x1, x2, sigma, mean, out);
}

// round 10
// speedup vs baseline: 1.6000x; 1.0239x over previous
#include <cuda_runtime.h>
#include <cuda_bf16.h>
#include <cstdint>

// GaussianKernel: N=32, R=128, F=128
// Gram form: D[i,j] = ||u_i||^2 - 2 u_i.v_j + ||v_j||^2,  u = x1 - mean, v = x2
// out = softmax_j( exp( exp(-D/(2 sigma^2)) ) )
//
// 128 blocks (1/SM), 256 threads = 8 warps. 4i x 4j register tile per thread.
// Norms fused into the fills via warp shfl trees (accurate + off the hot loop).
// Software-pipelined inner loop. Poly outer exp. Warp-local softmax.

#define N_B 32
#define R_DIM 128
#define F_DIM 128
#define TIB 32
#define X2_STRIDE 132   // padded row stride (floats): conflict-free LDS.128

__device__ __forceinline__ unsigned long long f32x2_fma(unsigned long long a, unsigned long long b, unsigned long long c) {
    unsigned long long r;
    asm("fma.rn.f32x2 %0, %1, %2, %3;" : "=l"(r) : "l"(a), "l"(b), "l"(c));
    return r;
}
__device__ __forceinline__ void f32x2_unpack(unsigned long long u, float& lo, float& hi) {
    asm("mov.b64 {%0, %1}, %2;" : "=f"(lo), "=f"(hi) : "l"(u));
}

// exp(x) for x in [0,1]: Taylor degree 10 (Horner). |err| <= 2.8e-8 abs.
__device__ __forceinline__ float exp01(float x) {
    float r = fmaf(2.75573192e-7f, x, 2.75573192e-6f);
    r = fmaf(r, x, 2.48015873e-5f);
    r = fmaf(r, x, 1.98412698e-4f);
    r = fmaf(r, x, 1.38888889e-3f);
    r = fmaf(r, x, 8.33333333e-3f);
    r = fmaf(r, x, 4.16666667e-2f);
    r = fmaf(r, x, 1.66666667e-1f);
    r = fmaf(r, x, 0.5f);
    r = fmaf(r, x, 1.0f);
    r = fmaf(r, x, 1.0f);
    return r;
}

__device__ __forceinline__ float warp_tree_sum(float s) {
    #pragma unroll
    for (int o = 16; o > 0; o >>= 1)
        s += __shfl_xor_sync(0xffffffffu, s, o);
    return s;
}

__global__ void __launch_bounds__(256)
gaussian_gram_v10(const float4* __restrict__ x1,
                  const float4* __restrict__ x2,
                  const float* __restrict__ sigma,
                  const float* __restrict__ mean,
                  float* __restrict__ out) {
    extern __shared__ float smem[];
    float* x2s   = smem;                         // [128][132]  v
    float* x1s   = x2s + R_DIM * X2_STRIDE;      // [32][128]   u = x1 - mean
    float* normu = x1s + TIB * F_DIM;            // [32]
    float* normv = normu + TIB;                  // [128]

    const int n    = blockIdx.y;
    const int i0   = blockIdx.x * TIB;
    const int t    = threadIdx.x;
    const int lane = t & 31;
    const int warp = t >> 5;                     // 0..7 -> i-rows 4w..4w+3

    const float mn = mean[0];
    const float sg = sigma[0];
    const float inv2s2 = 1.0f / (2.0f * sg * sg);

    // ---- batched fill: ALL LDGs first (MLP=20), then STS + fused norms ----
    {
        const float4* x2g = x2 + (size_t)n * (R_DIM * F_DIM / 4);
        const float4* x1g = x1 + ((size_t)n * R_DIM + i0) * (F_DIM / 4);
        float4 vb[16], ub[4];
        #pragma unroll
        for (int it = 0; it < 16; ++it) vb[it] = x2g[t + 256 * it];
        #pragma unroll
        for (int it = 0; it < 4; ++it)  ub[it] = x1g[t + 256 * it];

        // x2 store + normv: at iter 'it', warp w holds FULL row (w + 8*it)
        // (row = idx4>>5 is lane-invariant; lanes hold chunks c4 = 0..31)
        #pragma unroll
        for (int it = 0; it < 16; ++it) {
            int idx4 = t + 256 * it;
            int row  = idx4 >> 5;
            int c4   = idx4 & 31;
            float4 v = vb[it];
            *(float4*)&x2s[row * X2_STRIDE + c4 * 4] = v;
            float sq = v.x * v.x;
            sq = fmaf(v.y, v.y, sq);
            sq = fmaf(v.z, v.z, sq);
            sq = fmaf(v.w, v.w, sq);
            sq = warp_tree_sum(sq);
            if (lane == 0) normv[row] = sq;
        }
        // x1 store (u = x - mean) + normu, same per-warp full-row structure
        #pragma unroll
        for (int it = 0; it < 4; ++it) {
            int idx4 = t + 256 * it;
            int row  = idx4 >> 5;                // 0..31
            float4 v = ub[it];
            float4 u = make_float4(v.x - mn, v.y - mn, v.z - mn, v.w - mn);
            *(float4*)&x1s[idx4 * 4] = u;
            float sq = u.x * u.x;
            sq = fmaf(u.y, u.y, sq);
            sq = fmaf(u.z, u.z, sq);
            sq = fmaf(u.w, u.w, sq);
            sq = warp_tree_sum(sq);
            if (lane == 0) normu[row] = sq;
        }
    }
    __syncthreads();

    // ---- main loop: 4i x 4j tile, software-pipelined (prefetch dist 1) ----
    unsigned long long acc[4][4];
    #pragma unroll
    for (int r = 0; r < 4; ++r)
        #pragma unroll
        for (int q = 0; q < 4; ++q) acc[r][q] = 0ull;

    const ulonglong2* brow = (const ulonglong2*)&x2s[lane * X2_STRIDE];
    const float* arow = &x1s[warp * 4 * F_DIM];
    const int bq_stride = 32 * X2_STRIDE / 4;

    ulonglong2 bc[4], ac[4], bn[4], an[4];
    #pragma unroll
    for (int q = 0; q < 4; ++q) bc[q] = brow[q * bq_stride];
    #pragma unroll
    for (int r = 0; r < 4; ++r) ac[r] = *(const ulonglong2*)&arow[r * F_DIM];

    #pragma unroll 8
    for (int f4 = 0; f4 < F_DIM / 4; ++f4) {
        if (f4 + 1 < F_DIM / 4) {
            #pragma unroll
            for (int q = 0; q < 4; ++q) bn[q] = brow[q * bq_stride + f4 + 1];
            #pragma unroll
            for (int r = 0; r < 4; ++r) an[r] = *(const ulonglong2*)&arow[r * F_DIM + (f4 + 1) * 4];
        }
        #pragma unroll
        for (int r = 0; r < 4; ++r)
            #pragma unroll
            for (int q = 0; q < 4; ++q) {
                acc[r][q] = f32x2_fma(ac[r].x, bc[q].x, acc[r][q]);
                acc[r][q] = f32x2_fma(ac[r].y, bc[q].y, acc[r][q]);
            }
        #pragma unroll
        for (int q = 0; q < 4; ++q) bc[q] = bn[q];
        #pragma unroll
        for (int r = 0; r < 4; ++r) ac[r] = an[r];
    }

    // ---- epilogue ----
    float nv[4];
    #pragma unroll
    for (int q = 0; q < 4; ++q) nv[q] = normv[lane + 32 * q];
    float nu[4];
    #pragma unroll
    for (int r = 0; r < 4; ++r) nu[r] = normu[warp * 4 + r];

    float* outbase = out + ((size_t)n * R_DIM + i0 + warp * 4) * R_DIM;

    #pragma unroll
    for (int r = 0; r < 4; ++r) {
        float ex[4];
        float s = 0.0f;
        #pragma unroll
        for (int q = 0; q < 4; ++q) {
            float lo, hi; f32x2_unpack(acc[r][q], lo, hi);
            float D = fmaf(-2.0f, lo + hi, nu[r] + nv[q]);
            D = fmaxf(D, 0.0f);                  // true distance^2 >= 0
            float k = __expf(-D * inv2s2);       // in (0,1]
            ex[q] = exp01(k);                    // poly exp on FMA pipe
            s += ex[q];
        }
        s = warp_tree_sum(s);
        const float inv = __fdividef(1.0f, s);
        #pragma unroll
        for (int q = 0; q < 4; ++q)
            outbase[r * R_DIM + lane + 32 * q] = ex[q] * inv;
    }
}

extern "C" void kernel_launch(void* const* d_in, const int* in_sizes, int n_in,
                              void* d_out, int out_size) {
    const float4* x1    = (const float4*)d_in[0];
    const float4* x2    = (const float4*)d_in[1];
    const float*  sigma = (const float*)d_in[2];
    const float*  mean  = (const float*)d_in[3];
    float* out = (float*)d_out;

    const int smem_bytes = (R_DIM * X2_STRIDE + TIB * F_DIM + TIB + R_DIM) * (int)sizeof(float);
    cudaFuncSetAttribute(gaussian_gram_v10,
                         cudaFuncAttributeMaxDynamicSharedMemorySize, smem_bytes);

    dim3 grid(R_DIM / TIB, N_B);   // (4, 32) = 128 blocks -> 1 per SM
    dim3 block(256);
    gaussian_gram_v10<<<grid, block, smem_bytes>>>(x1, x2, sigma, mean, out);
}